// round 12
// baseline (speedup 1.0000x reference)
#include <cuda_runtime.h>
#include <cstdint>

#define NSEQ 8
#define QLEN 128
#define NQH 32
#define NKVH 8
#define GQA 4
#define HD 128
#define BLKSZ 16
#define MAXBLK 128
#define LTOT 2048
#define NSEG 4
#define TILEC 32

#define NCT 64
#define NTHREADS 128

// word strides
#define QW 68     // Q/K rows: 136 bf16 = 272B = 17*16B
#define VW 36     // V rows: 72 bf16 = 144B = 9*16B

#define OFF_QH 0
#define OFF_QL (OFF_QH + 64*QW)
#define OFF_KH (OFF_QL + 64*QW)
#define OFF_KL (OFF_KH + 64*QW)
#define OFF_VH (OFF_KL + 64*QW)
#define OFF_VL (OFF_VH + 128*VW)
#define SMEM_U32 (OFF_VL + 128*VW)
#define SMEM_BYTES (SMEM_U32*4)

static __device__ __forceinline__ void mma_bf16(float c[4], const uint32_t a[4],
                                                uint32_t b0, uint32_t b1) {
    asm volatile(
        "mma.sync.aligned.m16n8k16.row.col.f32.bf16.bf16.f32 "
        "{%0,%1,%2,%3}, {%4,%5,%6,%7}, {%8,%9}, {%0,%1,%2,%3};"
        : "+f"(c[0]), "+f"(c[1]), "+f"(c[2]), "+f"(c[3])
        : "r"(a[0]), "r"(a[1]), "r"(a[2]), "r"(a[3]), "r"(b0), "r"(b1));
}

static __device__ __forceinline__ void ldsm4(uint32_t& r0, uint32_t& r1,
                                             uint32_t& r2, uint32_t& r3, uint32_t addr) {
    asm volatile("ldmatrix.sync.aligned.m8n8.x4.shared.b16 {%0,%1,%2,%3}, [%4];"
        : "=r"(r0), "=r"(r1), "=r"(r2), "=r"(r3) : "r"(addr));
}

static __device__ __forceinline__ uint32_t smem_u32p(const void* p) {
    uint32_t a;
    asm("{ .reg .u64 t; cvta.to.shared.u64 t, %1; cvt.u32.u64 %0, t; }" : "=r"(a) : "l"(p));
    return a;
}

static __device__ __forceinline__ uint32_t pkbf2(float x0, float x1) {
    uint32_t r;
    asm("cvt.rn.bf16x2.f32 %0, %1, %2;" : "=r"(r) : "f"(x1), "f"(x0));
    return r;
}
static __device__ __forceinline__ void split2(float x0, float x1,
                                              uint32_t& hp, uint32_t& lp) {
    hp = pkbf2(x0, x1);
    float h0 = __uint_as_float(hp << 16);
    float h1 = __uint_as_float(hp & 0xffff0000u);
    lp = pkbf2(x0 - h0, x1 - h1);
}

__global__ void __launch_bounds__(NTHREADS, 2)
paged_seg_attn_qreg(const float* __restrict__ q,
                    const float* __restrict__ kc,
                    const float* __restrict__ vc,
                    const int*   __restrict__ bt,
                    const int*   __restrict__ seqlens,
                    const float* __restrict__ scale_p,
                    const float* __restrict__ softcap_p,
                    float*       __restrict__ out)
{
    extern __shared__ uint32_t smw[];
    const uint32_t smb = smem_u32p(smw);
    uint32_t* Qh = smw + OFF_QH;
    uint32_t* Ql = smw + OFF_QL;
    uint32_t* Kh = smw + OFF_KH;
    uint32_t* Kl = smw + OFF_KL;
    uint32_t* Vh = smw + OFF_VH;
    uint32_t* Vl = smw + OFF_VL;

    const int bx  = blockIdx.x;      // seg*2 + qhalf
    const int seg = bx >> 1;
    const int qh  = bx & 1;
    const int g   = blockIdx.y;
    const int z   = blockIdx.z;
    const int s   = z >> 3;
    const int kv  = z & 7;
    const int h   = kv * GQA + g;

    const int tid  = threadIdx.x;
    const int w    = tid >> 5;       // 0..3: q rows w*16..+15
    const int lane = tid & 31;
    const int gid  = lane >> 2;
    const int tig  = lane & 3;
    const int qb   = w * 16;

    const float scale = *scale_p;
    const float cap   = *softcap_p;
    const float tcoef = (cap > 0.f) ? (2.0f * scale / cap) : 0.f;
    const float n2cap = -2.0f * cap;

    const int seq_len   = seqlens[s];
    const int ctx       = seq_len - QLEN;
    const int span      = ((seq_len + NSEG * TILEC - 1) / (NSEG * TILEC)) * TILEC;
    const int seg_start = seg * span;
    const int seg_end   = min(seg_start + span, LTOT);

    const int kmax0 = ctx + qh * 64 + qb + gid;
    const int kmax1 = kmax0 + 8;

    const int* btrow = bt + s * MAXBLK;

    // ldmatrix bases (bytes)
    const int lrow16 = lane & 15;
    const int lhi    = lane >> 4;
    const uint32_t aQh = smb + OFF_QH*4 + (qb + lrow16)*272 + lhi*16;
    const uint32_t aQl = smb + OFF_QL*4 + (qb + lrow16)*272 + lhi*16;
    const int brow = (lane & 7) + ((lane >> 4) & 1) * 8;
    const int bkof = ((lane >> 3) & 1) * 8;
    const uint32_t bKh = smb + OFF_KH*4 + brow*272 + bkof*2;
    const uint32_t bKl = smb + OFF_KL*4 + brow*272 + bkof*2;
    const uint32_t bVh = smb + OFF_VH*4 + brow*144 + bkof*2;
    const uint32_t bVl = smb + OFF_VL*4 + brow*144 + bkof*2;

    // ---- stage Q: [row][d], hi/lo ----
    #pragma unroll
    for (int it = 0; it < 16; it++) {
        int i  = tid + it * NTHREADS;        // 0..2047
        int r  = i >> 5;
        int d4 = (i & 31) * 4;
        const float* src = q + ((size_t)(s * QLEN + qh * 64 + r) * NQH + h) * HD + d4;
        float4 v = *(const float4*)src;
        uint32_t h01, l01, h23, l23;
        split2(v.x, v.y, h01, l01);
        split2(v.z, v.w, h23, l23);
        int o2 = r * QW + (d4 >> 1);
        *(uint2*)(Qh + o2) = make_uint2(h01, h23);
        *(uint2*)(Ql + o2) = make_uint2(l01, l23);
    }
    __syncthreads();

    // ---- hoist Q fragments to registers (chunk-invariant) ----
    uint32_t qah[8][4], qal[8][4];
    #pragma unroll
    for (int ks = 0; ks < 8; ks++) {
        ldsm4(qah[ks][0], qah[ks][1], qah[ks][2], qah[ks][3], aQh + ks * 32);
        ldsm4(qal[ks][0], qal[ks][1], qal[ks][2], qal[ks][3], aQl + ks * 32);
    }

    float o[16][4];
    #pragma unroll
    for (int a = 0; a < 16; a++)
        #pragma unroll
        for (int b = 0; b < 4; b++) o[a][b] = 0.f;

    float pmax0 = 0.f, pmax1 = 0.f;

    for (int base = seg_start; base < seg_end; base += NCT) {
        __syncthreads();

        // ---- stage K: [tok][d], lanes sweep d-pairs ----
        #pragma unroll
        for (int it = 0; it < 8; it++) {
            int i  = tid + it * NTHREADS;    // 0..1023
            int d2 = i & 63;
            int t0 = (i >> 6) * 4;
            int pb = btrow[(base >> 4) + (t0 >> 4)];
            const float* kb0 = kc + (((size_t)pb * NKVH + kv) * HD + 2*d2) * BLKSZ + (t0 & 15);
            float4 va = *(const float4*)(kb0);
            float4 vb = *(const float4*)(kb0 + BLKSZ);
            float ea[4] = {va.x, va.y, va.z, va.w};
            float eb[4] = {vb.x, vb.y, vb.z, vb.w};
            #pragma unroll
            for (int j = 0; j < 4; j++) {
                uint32_t hp, lp;
                split2(ea[j], eb[j], hp, lp);
                Kh[(t0 + j) * QW + d2] = hp;
                Kl[(t0 + j) * QW + d2] = lp;
            }
        }
        // ---- stage V: [d][tok] ----
        #pragma unroll
        for (int it = 0; it < 8; it++) {
            int i  = tid + it * NTHREADS;    // 0..1023
            int d  = i >> 3;
            int th = i & 7;
            int pb = btrow[(base >> 4) + (th >> 1)];
            const float* vb0 = vc + (((size_t)pb * NKVH + kv) * HD + d) * BLKSZ + ((th & 1) * 8);
            float4 va = *(const float4*)(vb0);
            float4 vb = *(const float4*)(vb0 + 4);
            uint4 hv, lv;
            split2(va.x, va.y, hv.x, lv.x);
            split2(va.z, va.w, hv.y, lv.y);
            split2(vb.x, vb.y, hv.z, lv.z);
            split2(vb.z, vb.w, hv.w, lv.w);
            int o2 = d * VW + th * 4;
            *(uint4*)(Vh + o2) = hv;
            *(uint4*)(Vl + o2) = lv;
        }
        __syncthreads();

        // ---- QK: 16q x 64tok per warp (8 n-tiles), Q from regs ----
        float sacc[8][4];
        #pragma unroll
        for (int a = 0; a < 8; a++)
            #pragma unroll
            for (int b = 0; b < 4; b++) sacc[a][b] = 0.f;

        #pragma unroll
        for (int ks = 0; ks < 8; ks++) {
            #pragma unroll
            for (int ntp = 0; ntp < 4; ntp++) {
                uint32_t bh0A, bh1A, bh0B, bh1B, bl0A, bl1A, bl0B, bl1B;
                ldsm4(bh0A, bh1A, bh0B, bh1B, bKh + ntp * (16*272) + ks * 32);
                ldsm4(bl0A, bl1A, bl0B, bl1B, bKl + ntp * (16*272) + ks * 32);
                mma_bf16(sacc[2*ntp  ], qah[ks], bh0A, bh1A);
                mma_bf16(sacc[2*ntp  ], qal[ks], bh0A, bh1A);
                mma_bf16(sacc[2*ntp  ], qah[ks], bl0A, bl1A);
                mma_bf16(sacc[2*ntp+1], qah[ks], bh0B, bh1B);
                mma_bf16(sacc[2*ntp+1], qal[ks], bh0B, bh1B);
                mma_bf16(sacc[2*ntp+1], qah[ks], bl0B, bl1B);
            }
        }

        // ---- softcap + mask + p = exp(v - cap); pack PV A-frags ----
        uint32_t pah[4][4], pal[4][4];
        #pragma unroll
        for (int nt = 0; nt < 8; nt++) {
            float pe[4];
            #pragma unroll
            for (int e = 0; e < 4; e++) {
                int tpos = base + nt * 8 + 2 * tig + (e & 1);
                int kmax = (e < 2) ? kmax0 : kmax1;
                float raw = sacc[nt][e];
                float ex  = __expf(raw * tcoef);
                float p   = __expf(__fdividef(n2cap, ex + 1.f));
                bool ok   = (tpos <= kmax) && (tpos < seg_end);
                p = ok ? p : 0.f;
                if (e < 2) pmax0 = fmaxf(pmax0, p); else pmax1 = fmaxf(pmax1, p);
                pe[e] = p;
            }
            int j  = nt >> 1;
            int hi = (nt & 1) * 2;
            split2(pe[0], pe[1], pah[j][hi    ], pal[j][hi    ]);
            split2(pe[2], pe[3], pah[j][hi + 1], pal[j][hi + 1]);
        }

        // ---- PV: 16q x 128d x 64tok (4 k-steps), A in regs ----
        #pragma unroll
        for (int j = 0; j < 4; j++) {
            #pragma unroll
            for (int ntp = 0; ntp < 8; ntp++) {
                uint32_t bh0A, bh1A, bh0B, bh1B, bl0A, bl1A, bl0B, bl1B;
                ldsm4(bh0A, bh1A, bh0B, bh1B, bVh + ntp * (16*144) + j * 32);
                ldsm4(bl0A, bl1A, bl0B, bl1B, bVl + ntp * (16*144) + j * 32);
                mma_bf16(o[2*ntp  ], pah[j], bh0A, bh1A);
                mma_bf16(o[2*ntp  ], pal[j], bh0A, bh1A);
                mma_bf16(o[2*ntp  ], pah[j], bl0A, bl1A);
                mma_bf16(o[2*ntp+1], pah[j], bh0B, bh1B);
                mma_bf16(o[2*ntp+1], pal[j], bh0B, bh1B);
                mma_bf16(o[2*ntp+1], pah[j], bl0B, bl1B);
            }
        }
    }

    // ---- epilogue: lane-local pmax reduce, scale, store (no smem) ----
    #pragma unroll
    for (int off = 1; off < 4; off <<= 1) {
        pmax0 = fmaxf(pmax0, __shfl_xor_sync(0xffffffffu, pmax0, off));
        pmax1 = fmaxf(pmax1, __shfl_xor_sync(0xffffffffu, pmax1, off));
    }
    const float f0 = (pmax0 > 0.f) ? (1.0f / pmax0) : 0.f;
    const float f1 = (pmax1 > 0.f) ? (1.0f / pmax1) : 0.f;

    const int trow0 = s * QLEN + qh * 64 + qb + gid;
    float* o0 = out + (((size_t)trow0       * NQH + h) * NSEG + seg) * (size_t)HD;
    float* o1 = out + (((size_t)(trow0 + 8) * NQH + h) * NSEG + seg) * (size_t)HD;
    #pragma unroll
    for (int nt = 0; nt < 16; nt++) {
        int c = nt * 8 + 2 * tig;
        *(float2*)(o0 + c) = make_float2(o[nt][0] * f0, o[nt][1] * f0);
        *(float2*)(o1 + c) = make_float2(o[nt][2] * f1, o[nt][3] * f1);
    }
}

extern "C" void kernel_launch(void* const* d_in, const int* in_sizes, int n_in,
                              void* d_out, int out_size) {
    const float* q   = (const float*)d_in[0];
    const float* kc  = (const float*)d_in[1];
    const float* vc  = (const float*)d_in[2];
    const int*   bt  = (const int*)d_in[3];
    const int*   sl  = (const int*)d_in[4];
    const float* sc  = (const float*)d_in[6];
    const float* cap = (const float*)d_in[9];
    float* out = (float*)d_out;

    static int init_done = 0;
    if (!init_done) {
        cudaFuncSetAttribute(paged_seg_attn_qreg,
                             cudaFuncAttributeMaxDynamicSharedMemorySize, SMEM_BYTES);
        init_done = 1;
    }
    dim3 grid(NSEG * 2, GQA, NSEQ * NKVH);
    paged_seg_attn_qreg<<<grid, NTHREADS, SMEM_BYTES>>>(q, kc, vc, bt, sl, sc, cap, out);
}

// round 13
// speedup vs baseline: 1.2956x; 1.2956x over previous
#include <cuda_runtime.h>
#include <cstdint>

#define NSEQ 8
#define QLEN 128
#define NQH 32
#define NKVH 8
#define GQA 4
#define HD 128
#define BLKSZ 16
#define MAXBLK 128
#define LTOT 2048
#define NSEG 4
#define TILEC 32

#define NCT 32
#define NTHREADS 256

// word strides
#define QW 68     // Q/K rows: 136 bf16 = 272B = 17*16B (conflict-free ldsm)
#define VW 20     // V rows: 40 bf16 = 80B = 5*16B (conflict-free ldsm)

#define OFF_QH 0
#define OFF_QL (OFF_QH + 128*QW)
#define OFF_KH (OFF_QL + 128*QW)
#define OFF_KL (OFF_KH + NCT*QW)
#define OFF_VH (OFF_KL + NCT*QW)
#define OFF_VL (OFF_VH + 128*VW)
#define SMEM_U32 (OFF_VL + 128*VW)
#define SMEM_BYTES (SMEM_U32*4)

static __device__ __forceinline__ void mma_bf16(float c[4], const uint32_t a[4],
                                                uint32_t b0, uint32_t b1) {
    asm volatile(
        "mma.sync.aligned.m16n8k16.row.col.f32.bf16.bf16.f32 "
        "{%0,%1,%2,%3}, {%4,%5,%6,%7}, {%8,%9}, {%0,%1,%2,%3};"
        : "+f"(c[0]), "+f"(c[1]), "+f"(c[2]), "+f"(c[3])
        : "r"(a[0]), "r"(a[1]), "r"(a[2]), "r"(a[3]), "r"(b0), "r"(b1));
}

static __device__ __forceinline__ void ldsm4(uint32_t& r0, uint32_t& r1,
                                             uint32_t& r2, uint32_t& r3, uint32_t addr) {
    asm volatile("ldmatrix.sync.aligned.m8n8.x4.shared.b16 {%0,%1,%2,%3}, [%4];"
        : "=r"(r0), "=r"(r1), "=r"(r2), "=r"(r3) : "r"(addr));
}

static __device__ __forceinline__ uint32_t smem_u32p(const void* p) {
    uint32_t a;
    asm("{ .reg .u64 t; cvta.to.shared.u64 t, %1; cvt.u32.u64 %0, t; }" : "=r"(a) : "l"(p));
    return a;
}

static __device__ __forceinline__ uint32_t pkbf2(float x0, float x1) {
    uint32_t r;
    asm("cvt.rn.bf16x2.f32 %0, %1, %2;" : "=r"(r) : "f"(x1), "f"(x0));
    return r;
}
static __device__ __forceinline__ void split2(float x0, float x1,
                                              uint32_t& hp, uint32_t& lp) {
    hp = pkbf2(x0, x1);
    float h0 = __uint_as_float(hp << 16);
    float h1 = __uint_as_float(hp & 0xffff0000u);
    lp = pkbf2(x0 - h0, x1 - h1);
}

__global__ void __launch_bounds__(NTHREADS, 2)
paged_seg_attn_gm(const float* __restrict__ q,
                  const float* __restrict__ kc,
                  const float* __restrict__ vc,
                  const int*   __restrict__ bt,
                  const int*   __restrict__ seqlens,
                  const float* __restrict__ scale_p,
                  const float* __restrict__ softcap_p,
                  float*       __restrict__ out)
{
    extern __shared__ uint32_t smw[];
    const uint32_t smb = smem_u32p(smw);
    uint32_t* Qh = smw + OFF_QH;
    uint32_t* Ql = smw + OFF_QL;
    uint32_t* Kh = smw + OFF_KH;
    uint32_t* Kl = smw + OFF_KL;
    uint32_t* Vh = smw + OFF_VH;
    uint32_t* Vl = smw + OFF_VL;

    const int bx  = blockIdx.x;      // seg*2 + qhalf
    const int seg = bx >> 1;
    const int qh  = bx & 1;
    const int gp  = blockIdx.y;      // g-pair: heads kv*4 + 2gp, +1
    const int z   = blockIdx.z;
    const int s   = z >> 3;
    const int kv  = z & 7;

    const int tid  = threadIdx.x;
    const int w    = tid >> 5;       // 0..7: CTA q rows w*16..+15 (of 128)
    const int lane = tid & 31;
    const int gid  = lane >> 2;
    const int tig  = lane & 3;
    const int qb   = w * 16;

    const int h    = kv * GQA + gp * 2 + (qb >> 6);   // head of this warp's rows
    const int qrow = qb & 63;                          // row within the 64-q half

    const float scale = *scale_p;
    const float cap   = *softcap_p;
    const float tcoef = (cap > 0.f) ? (2.0f * scale / cap) : 0.f;
    const float n2cap = -2.0f * cap;

    const int seq_len   = seqlens[s];
    const int ctx       = seq_len - QLEN;
    const int span      = ((seq_len + NSEG * TILEC - 1) / (NSEG * TILEC)) * TILEC;
    const int seg_start = seg * span;
    const int seg_end   = min(seg_start + span, LTOT);

    const int kmax0 = ctx + qh * 64 + qrow + gid;
    const int kmax1 = kmax0 + 8;

    const int* btrow = bt + s * MAXBLK;

    // ldmatrix bases (bytes)
    const int lrow16 = lane & 15;
    const int lhi    = lane >> 4;
    const uint32_t aQh = smb + OFF_QH*4 + (qb + lrow16)*272 + lhi*16;
    const uint32_t aQl = smb + OFF_QL*4 + (qb + lrow16)*272 + lhi*16;
    const int brow = (lane & 7) + ((lane >> 4) & 1) * 8;
    const int bkof = ((lane >> 3) & 1) * 8;
    const uint32_t bKh = smb + OFF_KH*4 + brow*272 + bkof*2;
    const uint32_t bKl = smb + OFF_KL*4 + brow*272 + bkof*2;
    const uint32_t bVh = smb + OFF_VH*4 + brow*80 + bkof*2;
    const uint32_t bVl = smb + OFF_VL*4 + brow*80 + bkof*2;

    // ---- stage Q: 128 rows (2 heads x 64), [row][d], hi/lo ----
    #pragma unroll
    for (int it = 0; it < 16; it++) {
        int i  = tid + it * NTHREADS;        // 0..4095
        int r  = i >> 5;                     // 0..127
        int d4 = (i & 31) * 4;
        int hh = kv * GQA + gp * 2 + (r >> 6);
        const float* src = q + ((size_t)(s * QLEN + qh * 64 + (r & 63)) * NQH + hh) * HD + d4;
        float4 v = *(const float4*)src;
        uint32_t h01, l01, h23, l23;
        split2(v.x, v.y, h01, l01);
        split2(v.z, v.w, h23, l23);
        int o2 = r * QW + (d4 >> 1);
        *(uint2*)(Qh + o2) = make_uint2(h01, h23);
        *(uint2*)(Ql + o2) = make_uint2(l01, l23);
    }

    float o[16][4];
    #pragma unroll
    for (int a = 0; a < 16; a++)
        #pragma unroll
        for (int b = 0; b < 4; b++) o[a][b] = 0.f;

    float pmax0 = 0.f, pmax1 = 0.f;

    for (int base = seg_start; base < seg_end; base += NCT) {
        __syncthreads();

        // ---- stage K: [tok][d], lanes sweep d-pairs; 32 toks ----
        #pragma unroll
        for (int it = 0; it < 2; it++) {
            int i  = tid + it * NTHREADS;    // 0..511
            int d2 = i & 63;
            int t0 = (i >> 6) * 4;           // 0..28
            int pb = btrow[(base >> 4) + (t0 >> 4)];
            const float* kb0 = kc + (((size_t)pb * NKVH + kv) * HD + 2*d2) * BLKSZ + (t0 & 15);
            float4 va = *(const float4*)(kb0);
            float4 vb = *(const float4*)(kb0 + BLKSZ);
            float ea[4] = {va.x, va.y, va.z, va.w};
            float eb[4] = {vb.x, vb.y, vb.z, vb.w};
            #pragma unroll
            for (int j = 0; j < 4; j++) {
                uint32_t hp, lp;
                split2(ea[j], eb[j], hp, lp);
                Kh[(t0 + j) * QW + d2] = hp;
                Kl[(t0 + j) * QW + d2] = lp;
            }
        }
        // ---- stage V: [d][tok]; 128 d x 32 toks ----
        #pragma unroll
        for (int it = 0; it < 2; it++) {
            int i  = tid + it * NTHREADS;    // 0..511
            int d  = i >> 2;                 // 0..127
            int th = i & 3;                  // 8-tok group
            int pb = btrow[(base >> 4) + (th >> 1)];
            const float* vb0 = vc + (((size_t)pb * NKVH + kv) * HD + d) * BLKSZ + ((th & 1) * 8);
            float4 va = *(const float4*)(vb0);
            float4 vb = *(const float4*)(vb0 + 4);
            uint4 hv, lv;
            split2(va.x, va.y, hv.x, lv.x);
            split2(va.z, va.w, hv.y, lv.y);
            split2(vb.x, vb.y, hv.z, lv.z);
            split2(vb.z, vb.w, hv.w, lv.w);
            *(uint4*)(Vh + d * VW + th * 4) = hv;
            *(uint4*)(Vl + d * VW + th * 4) = lv;
        }
        __syncthreads();

        // ---- QK: 16q x 32tok per warp, 8 k16 steps, 3-term ----
        float sacc[4][4];
        #pragma unroll
        for (int a = 0; a < 4; a++)
            #pragma unroll
            for (int b = 0; b < 4; b++) sacc[a][b] = 0.f;

        #pragma unroll
        for (int ks = 0; ks < 8; ks++) {
            uint32_t ah[4], al[4];
            ldsm4(ah[0], ah[1], ah[2], ah[3], aQh + ks * 32);
            ldsm4(al[0], al[1], al[2], al[3], aQl + ks * 32);
            #pragma unroll
            for (int ntp = 0; ntp < 2; ntp++) {
                uint32_t bh0A, bh1A, bh0B, bh1B, bl0A, bl1A, bl0B, bl1B;
                ldsm4(bh0A, bh1A, bh0B, bh1B, bKh + ntp * (16*272) + ks * 32);
                ldsm4(bl0A, bl1A, bl0B, bl1B, bKl + ntp * (16*272) + ks * 32);
                mma_bf16(sacc[2*ntp  ], ah, bh0A, bh1A);
                mma_bf16(sacc[2*ntp  ], al, bh0A, bh1A);
                mma_bf16(sacc[2*ntp  ], ah, bl0A, bl1A);
                mma_bf16(sacc[2*ntp+1], ah, bh0B, bh1B);
                mma_bf16(sacc[2*ntp+1], al, bh0B, bh1B);
                mma_bf16(sacc[2*ntp+1], ah, bl0B, bl1B);
            }
        }

        // ---- softcap + mask + p = exp(v - cap); PV per j (frees sacc early) ----
        #pragma unroll
        for (int j = 0; j < 2; j++) {
            uint32_t pah[4], pal[4];
            #pragma unroll
            for (int t = 0; t < 2; t++) {
                int nt = 2 * j + t;
                float pe[4];
                #pragma unroll
                for (int e = 0; e < 4; e++) {
                    int tpos = base + nt * 8 + 2 * tig + (e & 1);
                    int kmax = (e < 2) ? kmax0 : kmax1;
                    float raw = sacc[nt][e];
                    float ex  = __expf(raw * tcoef);
                    float p   = __expf(__fdividef(n2cap, ex + 1.f));
                    bool ok   = (tpos <= kmax) && (tpos < seg_end);
                    p = ok ? p : 0.f;
                    if (e < 2) pmax0 = fmaxf(pmax0, p); else pmax1 = fmaxf(pmax1, p);
                    pe[e] = p;
                }
                split2(pe[0], pe[1], pah[2*t    ], pal[2*t    ]);
                split2(pe[2], pe[3], pah[2*t + 1], pal[2*t + 1]);
            }
            // PV k-step j: 16q x 128d over toks 16j..16j+15
            #pragma unroll
            for (int ntp = 0; ntp < 8; ntp++) {
                uint32_t bh0A, bh1A, bh0B, bh1B, bl0A, bl1A, bl0B, bl1B;
                ldsm4(bh0A, bh1A, bh0B, bh1B, bVh + ntp * (16*80) + j * 32);
                ldsm4(bl0A, bl1A, bl0B, bl1B, bVl + ntp * (16*80) + j * 32);
                mma_bf16(o[2*ntp  ], pah, bh0A, bh1A);
                mma_bf16(o[2*ntp  ], pal, bh0A, bh1A);
                mma_bf16(o[2*ntp  ], pah, bl0A, bl1A);
                mma_bf16(o[2*ntp+1], pah, bh0B, bh1B);
                mma_bf16(o[2*ntp+1], pal, bh0B, bh1B);
                mma_bf16(o[2*ntp+1], pah, bl0B, bl1B);
            }
        }
    }

    // ---- epilogue: warp-local pmax reduce, scale, store (no syncs) ----
    #pragma unroll
    for (int off = 1; off < 4; off <<= 1) {
        pmax0 = fmaxf(pmax0, __shfl_xor_sync(0xffffffffu, pmax0, off));
        pmax1 = fmaxf(pmax1, __shfl_xor_sync(0xffffffffu, pmax1, off));
    }
    const float f0 = (pmax0 > 0.f) ? (1.0f / pmax0) : 0.f;
    const float f1 = (pmax1 > 0.f) ? (1.0f / pmax1) : 0.f;

    const int trow0 = s * QLEN + qh * 64 + qrow + gid;
    float* o0 = out + (((size_t)trow0       * NQH + h) * NSEG + seg) * (size_t)HD;
    float* o1 = out + (((size_t)(trow0 + 8) * NQH + h) * NSEG + seg) * (size_t)HD;
    #pragma unroll
    for (int nt = 0; nt < 16; nt++) {
        int c = nt * 8 + 2 * tig;
        *(float2*)(o0 + c) = make_float2(o[nt][0] * f0, o[nt][1] * f0);
        *(float2*)(o1 + c) = make_float2(o[nt][2] * f1, o[nt][3] * f1);
    }
}

extern "C" void kernel_launch(void* const* d_in, const int* in_sizes, int n_in,
                              void* d_out, int out_size) {
    const float* q   = (const float*)d_in[0];
    const float* kc  = (const float*)d_in[1];
    const float* vc  = (const float*)d_in[2];
    const int*   bt  = (const int*)d_in[3];
    const int*   sl  = (const int*)d_in[4];
    const float* sc  = (const float*)d_in[6];
    const float* cap = (const float*)d_in[9];
    float* out = (float*)d_out;

    static int init_done = 0;
    if (!init_done) {
        cudaFuncSetAttribute(paged_seg_attn_gm,
                             cudaFuncAttributeMaxDynamicSharedMemorySize, SMEM_BYTES);
        init_done = 1;
    }
    dim3 grid(NSEG * 2, 2, NSEQ * NKVH);
    paged_seg_attn_gm<<<grid, NTHREADS, SMEM_BYTES>>>(q, kc, vc, bt, sl, sc, cap, out);
}